// round 13
// baseline (speedup 1.0000x reference)
#include <cuda_runtime.h>
#include <cuda_fp16.h>
#include <cstdint>

#define BATCH 128
#define SEQ   2048
#define KDIM  128
#define CAPS  32
#define DCAP  16
#define MCOLS 512
#define NTILES 8          // CTAs per batch; each CTA covers 256 rows
#define NPART 16          // y partial slots = tile*2 + half
#define NSUB  4           // 32-row subtiles per 128-row half

#define XST 136           // x tile stride (u16): 272B rows, ldsm conflict-free
#define PST 40            // P tile stride (u16): [n][c] layout, 80B rows
// smem byte offsets
#define SM_XH 0           // [2 halves][32][XST] fp16 hi
#define SM_XL 17408       // lo
#define SM_WH 34816       // [32][XST] fp16 hi
#define SM_WL 43520
#define SM_PH 52224       // [2 halves][32 n][PST c] fp16 (hi only)
#define SM_SX 57344       // softmax row-sum exchange [2][2][32] float
#define SM_TOTAL 57856

__device__ __forceinline__ uint32_t smem_u32(const void* p) {
    uint32_t a;
    asm("{ .reg .u64 t; cvta.to.shared.u64 t, %1; cvt.u32.u64 %0, t; }"
        : "=r"(a) : "l"(p));
    return a;
}
__device__ __forceinline__ void ldsm_x4(uint32_t a, uint32_t r[4]) {
    asm volatile("ldmatrix.sync.aligned.m8n8.x4.shared.b16 {%0,%1,%2,%3}, [%4];"
        : "=r"(r[0]), "=r"(r[1]), "=r"(r[2]), "=r"(r[3]) : "r"(a));
}
__device__ __forceinline__ void ldsm_x4t(uint32_t a, uint32_t r[4]) {
    asm volatile("ldmatrix.sync.aligned.m8n8.x4.trans.shared.b16 {%0,%1,%2,%3}, [%4];"
        : "=r"(r[0]), "=r"(r[1]), "=r"(r[2]), "=r"(r[3]) : "r"(a));
}
__device__ __forceinline__ void stsm_x4(uint32_t a, uint32_t r0, uint32_t r1,
                                        uint32_t r2, uint32_t r3) {
    asm volatile("stmatrix.sync.aligned.m8n8.x4.shared.b16 [%0], {%1,%2,%3,%4};"
        :: "r"(a), "r"(r0), "r"(r1), "r"(r2), "r"(r3) : "memory");
}
__device__ __forceinline__ void mma_f16(float c[4], const uint32_t a[4],
                                        uint32_t b0, uint32_t b1) {
    asm volatile("mma.sync.aligned.m16n8k16.row.col.f32.f16.f16.f32 "
        "{%0,%1,%2,%3}, {%4,%5,%6,%7}, {%8,%9}, {%0,%1,%2,%3};"
        : "+f"(c[0]), "+f"(c[1]), "+f"(c[2]), "+f"(c[3])
        : "r"(a[0]), "r"(a[1]), "r"(a[2]), "r"(a[3]), "r"(b0), "r"(b1));
}
__device__ __forceinline__ uint32_t pack_h2(__half a, __half b) {
    __half2 h = __halves2half2(a, b);
    return *(uint32_t*)&h;
}
#define BARH(id) asm volatile("bar.sync %0, 128;" :: "r"(id) : "memory")

// ---- scratch ----
__device__ float g_S2[BATCH][2][KDIM];
__device__ float g_W2[BATCH][CAPS][KDIM];
__device__ unsigned short g_W2h[BATCH][CAPS * XST];
__device__ unsigned short g_W2l[BATCH][CAPS * XST];
__device__ float g_ypart[BATCH][NPART][CAPS * KDIM];
__device__ float g_y[BATCH][CAPS * KDIM];

// ---- W2[b][c][k] = sum_d kernel[k, c*16+d] * o[b,c,d]; + fp16 hi/lo split ----
__device__ __forceinline__ void compute_W2(int b, int t, const float* os,
                                           const float* __restrict__ w) {
#pragma unroll
    for (int i = 0; i < 8; ++i) {
        int idx = t + i * 512;
        int c = idx >> 7, k = idx & 127;
        const float4* wr = (const float4*)(w + k * MCOLS + c * DCAP);
        const float4* ov = (const float4*)(os + c * DCAP);
        float acc = 0.f;
#pragma unroll
        for (int q = 0; q < 4; ++q) {
            float4 a = wr[q], o4 = ov[q];
            acc += a.x * o4.x + a.y * o4.y + a.z * o4.z + a.w * o4.w;
        }
        g_W2[b][c][k] = acc;
        __half hh = __float2half_rn(acc);
        __half ll = __float2half_rn(acc - __half2float(hh));
        g_W2h[b][c * XST + k] = *(unsigned short*)&hh;
        g_W2l[b][c * XST + k] = *(unsigned short*)&ll;
    }
}

// ============================================================
// Kernel 1a: partial column sums of x. grid (2, BATCH), 512 thr.
// ============================================================
__global__ void __launch_bounds__(512) k_red(const float* __restrict__ x) {
    int b = blockIdx.y, half = blockIdx.x, t = threadIdx.x;
    __shared__ float4 red[16][32];
    int c4 = t & 31, rg = t >> 5;
    const float4* xp = (const float4*)(x + ((size_t)b * SEQ + half * 1024) * KDIM);
    float4 s = make_float4(0.f, 0.f, 0.f, 0.f);
#pragma unroll 8
    for (int j = 0; j < 64; ++j) {
        float4 v = xp[(rg + 16 * j) * 32 + c4];
        s.x += v.x; s.y += v.y; s.z += v.z; s.w += v.w;
    }
    red[rg][c4] = s;
    __syncthreads();
    if (t < 32) {
        float4 a = red[0][t];
#pragma unroll
        for (int r = 1; r < 16; ++r) {
            float4 v = red[r][t];
            a.x += v.x; a.y += v.y; a.z += v.z; a.w += v.w;
        }
        *(float4*)&g_S2[b][half][t * 4] = a;
    }
}

// ============================================================
// Kernel 1b: o1 = squash((1/32)*S@kernel) + fused W2. grid 128, 512 thr.
// ============================================================
__global__ void k_ow(const float* __restrict__ w) {
    int b = blockIdx.x, t = threadIdx.x;
    __shared__ float S[KDIM];
    __shared__ float os[MCOLS];
    if (t < KDIM)
        S[t] = (g_S2[b][0][t] + g_S2[b][1][t]) * (1.f / 32.f);
    __syncthreads();
    float acc = 0.f;
#pragma unroll 4
    for (int k = 0; k < KDIM; ++k) acc += S[k] * w[k * MCOLS + t];
    float sq = acc * acc;
#pragma unroll
    for (int off = 8; off >= 1; off >>= 1)
        sq += __shfl_xor_sync(0xffffffffu, sq, off, 16);
    float s2 = sq + 1e-7f;
    float scale = sqrtf(s2) / (0.5f + s2);
    os[t] = scale * acc;
    __syncthreads();
    compute_W2(b, t, os, w);
}

// ============================================================
// Kernel 2: routing iteration — fp16 split, 2-combo both phases,
// stmatrix P epilogue. grid (NTILES, BATCH), 256 thr, 3 CTAs/SM.
// ============================================================
__global__ void __launch_bounds__(256, 3) k_iter_mma(const float* __restrict__ x) {
    extern __shared__ char sm[];
    uint32_t sb = smem_u32(sm);
    int b = blockIdx.y, tile = blockIdx.x, t = threadIdx.x;
    int wid = t >> 5, l = t & 31;
    int h = wid >> 2, wl = wid & 3;
    int barid = 1 + h;
    int ht = t & 127;

    // cooperative W tile load (all 256 threads)
    {
        const uint32_t* wh = (const uint32_t*)g_W2h[b];
        const uint32_t* wls = (const uint32_t*)g_W2l[b];
        uint32_t* swh = (uint32_t*)(sm + SM_WH);
        uint32_t* swl = (uint32_t*)(sm + SM_WL);
        for (int i = t; i < CAPS * XST / 2; i += 256) {
            swh[i] = wh[i]; swl[i] = wls[i];
        }
    }
    __syncthreads();

    uint32_t xh_base = sb + SM_XH + (uint32_t)h * 32 * XST * 2;
    uint32_t p_base  = sb + SM_PH + (uint32_t)h * 32 * PST * 2;  // [n][c]
    float* sx = (float*)(sm + SM_SX) + h * 64;

    int rh = wl & 1, ch = wl >> 1;
    int r0 = rh * 16, c0 = ch * 16;
    int cw = wl & 1, kw = wl >> 1;
    int m0c = cw * 16;

    float c2[8][4];
#pragma unroll
    for (int j = 0; j < 8; ++j)
#pragma unroll
        for (int e = 0; e < 4; ++e) c2[j][e] = 0.f;

    for (int sub = 0; sub < NSUB; ++sub) {
        BARH(barid);   // buffers free

        // ---- load 32-row x subtile, split fp16 hi/lo ----
        {
            const float4* xb = (const float4*)(
                x + ((size_t)(b * SEQ + tile * 256 + h * 128 + sub * 32)) * KDIM);
            uint32_t* xhp = (uint32_t*)(sm + SM_XH) + h * 32 * XST / 2;
            uint32_t* xlp = (uint32_t*)(sm + SM_XL) + h * 32 * XST / 2;
#pragma unroll
            for (int i = 0; i < 8; ++i) {
                int lin = ht + i * 128;
                int row = lin >> 5, c4 = lin & 31;
                float4 v = xb[row * 32 + c4];
                __half hx = __float2half_rn(v.x), hy = __float2half_rn(v.y);
                __half hz = __float2half_rn(v.z), hw = __float2half_rn(v.w);
                uint32_t h01 = pack_h2(hx, hy);
                uint32_t h23 = pack_h2(hz, hw);
                uint32_t l01 = pack_h2(__float2half_rn(v.x - __half2float(hx)),
                                       __float2half_rn(v.y - __half2float(hy)));
                uint32_t l23 = pack_h2(__float2half_rn(v.z - __half2float(hz)),
                                       __float2half_rn(v.w - __half2float(hw)));
                int u = (row * XST + c4 * 4) >> 1;
                *(uint2*)&xhp[u] = make_uint2(h01, h23);
                *(uint2*)&xlp[u] = make_uint2(l01, l23);
            }
        }
        BARH(barid);   // x ready

        // ---- phase 1: logits[16n][16c] per warp = Xh @ (Wh+Wl)^T ----
        float c1[2][4];
#pragma unroll
        for (int j = 0; j < 2; ++j)
#pragma unroll
            for (int e = 0; e < 4; ++e) c1[j][e] = 0.f;

#pragma unroll
        for (int ks = 0; ks < 8; ++ks) {
            int k0 = ks * 16;
            uint32_t aaddr = xh_base + (uint32_t)(r0 + (l & 15)) * (XST * 2)
                           + k0 * 2 + (l >> 4) * 16;
            uint32_t ah[4];
            ldsm_x4(aaddr, ah);
            uint32_t baddr = sb + SM_WH
                + (uint32_t)(c0 + (l >> 4) * 8 + (l & 7)) * (XST * 2)
                + k0 * 2 + ((l >> 3) & 1) * 16;
            uint32_t bh[4], bl[4];
            ldsm_x4(baddr, bh);
            ldsm_x4(baddr + (SM_WL - SM_WH), bl);
            mma_f16(c1[0], ah, bh[0], bh[1]);
            mma_f16(c1[1], ah, bh[2], bh[3]);
            mma_f16(c1[0], ah, bl[0], bl[1]);
            mma_f16(c1[1], ah, bl[2], bl[3]);
        }

        // ---- softmax (no-max; exact-math identical): exp + cross-warp sums ----
        {
#pragma unroll
            for (int j = 0; j < 2; ++j)
#pragma unroll
                for (int e = 0; e < 4; ++e) c1[j][e] = __expf(c1[j][e]);
            float s0 = c1[0][0] + c1[0][1] + c1[1][0] + c1[1][1];
            float s1 = c1[0][2] + c1[0][3] + c1[1][2] + c1[1][3];
            s0 += __shfl_xor_sync(0xffffffffu, s0, 1);
            s0 += __shfl_xor_sync(0xffffffffu, s0, 2);
            s1 += __shfl_xor_sync(0xffffffffu, s1, 1);
            s1 += __shfl_xor_sync(0xffffffffu, s1, 2);
            if ((l & 3) == 0) {
                sx[ch * 32 + r0 + (l >> 2)]     = s0;
                sx[ch * 32 + r0 + (l >> 2) + 8] = s1;
            }
        }
        BARH(barid);   // sums ready

        // ---- finish softmax + write P[n][c] via one stmatrix.x4 ----
        {
            int nr = r0 + (l >> 2);
            float inv0 = 1.f / (sx[nr] + sx[32 + nr]);
            float inv1 = 1.f / (sx[nr + 8] + sx[32 + nr + 8]);
            uint32_t d0 = pack_h2(__float2half_rn(c1[0][0] * inv0),
                                  __float2half_rn(c1[0][1] * inv0));
            uint32_t d1 = pack_h2(__float2half_rn(c1[1][0] * inv0),
                                  __float2half_rn(c1[1][1] * inv0));
            uint32_t d2 = pack_h2(__float2half_rn(c1[0][2] * inv1),
                                  __float2half_rn(c1[0][3] * inv1));
            uint32_t d3 = pack_h2(__float2half_rn(c1[1][2] * inv1),
                                  __float2half_rn(c1[1][3] * inv1));
            uint32_t addr = p_base
                + (uint32_t)(r0 + ((l >> 4) & 1) * 8 + (l & 7)) * (PST * 2)
                + (c0 + ((l >> 3) & 1) * 8) * 2;
            stsm_x4(addr, d0, d1, d2, d3);
        }
        BARH(barid);   // P ready

        // ---- phase 2: Y^T[16c][64k per warp] += P^T @ (Xh+Xl) ----
#pragma unroll
        for (int ns = 0; ns < 2; ++ns) {
            int n0 = ns * 16;
            // A = P^T (c x n) from [n][c] storage via trans ldsm
            uint32_t aaddr = p_base
                + (uint32_t)(n0 + ((l >> 4) & 1) * 8 + (l & 7)) * (PST * 2)
                + (m0c + ((l >> 3) & 1) * 8) * 2;
            uint32_t ah[4];
            ldsm_x4t(aaddr, ah);
#pragma unroll
            for (int qq = 0; qq < 2; ++qq) {
                uint32_t bh[2][4], bl[2][4];
#pragma unroll
                for (int q = 0; q < 2; ++q) {
                    int k0 = kw * 64 + (qq * 2 + q) * 16;
                    uint32_t baddr = xh_base
                        + (uint32_t)(n0 + (l & 15)) * (XST * 2)
                        + (k0 + 8 * (l >> 4)) * 2;
                    ldsm_x4t(baddr, bh[q]);
                    ldsm_x4t(baddr + (SM_XL - SM_XH), bl[q]);
                }
#pragma unroll
                for (int q = 0; q < 2; ++q) {
                    int j = (qq * 2 + q) * 2;
                    mma_f16(c2[j],     ah, bh[q][0], bh[q][1]);
                    mma_f16(c2[j + 1], ah, bh[q][2], bh[q][3]);
                    mma_f16(c2[j],     ah, bl[q][0], bl[q][1]);
                    mma_f16(c2[j + 1], ah, bl[q][2], bl[q][3]);
                }
            }
        }
    }

    // ---- write y partial: slot = tile*2 + h ----
    {
        float* yo = &g_ypart[b][tile * 2 + h][0];
        int cr = m0c + (l >> 2);
#pragma unroll
        for (int q = 0; q < 4; ++q) {
            int k = kw * 64 + q * 16 + (l & 3) * 2;
            yo[cr * KDIM + k]            = c2[2 * q][0];
            yo[cr * KDIM + k + 1]        = c2[2 * q][1];
            yo[(cr + 8) * KDIM + k]      = c2[2 * q][2];
            yo[(cr + 8) * KDIM + k + 1]  = c2[2 * q][3];
            yo[cr * KDIM + k + 8]        = c2[2 * q + 1][0];
            yo[cr * KDIM + k + 9]        = c2[2 * q + 1][1];
            yo[(cr + 8) * KDIM + k + 8]  = c2[2 * q + 1][2];
            yo[(cr + 8) * KDIM + k + 9]  = c2[2 * q + 1][3];
        }
    }
}

// ============================================================
// Kernel 3: sum 16 y partials (float4). grid (2, BATCH), 512 thr.
// ============================================================
__global__ void k_yred() {
    int b = blockIdx.y, t = threadIdx.x;
    int i4 = blockIdx.x * 512 + t;
    float4 s = make_float4(0.f, 0.f, 0.f, 0.f);
#pragma unroll
    for (int p = 0; p < NPART; ++p) {
        float4 v = ((const float4*)g_ypart[b][p])[i4];
        s.x += v.x; s.y += v.y; s.z += v.z; s.w += v.w;
    }
    ((float4*)g_y[b])[i4] = s;
}

// ============================================================
// Kernel 4: u = y @ kernel, squash; output or fused W2. grid 128, 512 thr.
// ============================================================
__global__ void k_fin(const float* __restrict__ w, float* __restrict__ out) {
    int b = blockIdx.x, t = threadIdx.x;
    __shared__ float ys[CAPS * KDIM];
    __shared__ float os[MCOLS];
#pragma unroll
    for (int i = 0; i < 8; ++i) ys[t + i * 512] = g_y[b][t + i * 512];
    __syncthreads();
    int c = t >> 4;
    const float* yr = &ys[c * KDIM];
    float acc = 0.f;
#pragma unroll 8
    for (int k = 0; k < KDIM; ++k) acc += yr[k] * w[k * MCOLS + t];
    float sq = acc * acc;
#pragma unroll
    for (int off = 8; off >= 1; off >>= 1)
        sq += __shfl_xor_sync(0xffffffffu, sq, off, 16);
    float s2 = sq + 1e-7f;
    float scale = sqrtf(s2) / (0.5f + s2);
    float val = scale * acc;
    if (out) {
        out[b * MCOLS + t] = val;
    } else {
        os[t] = val;
        __syncthreads();
        compute_W2(b, t, os, w);
    }
}

extern "C" void kernel_launch(void* const* d_in, const int* in_sizes, int n_in,
                              void* d_out, int out_size) {
    const float* x = (const float*)d_in[0];
    const float* w = (const float*)d_in[1];
    if (n_in >= 2 && in_sizes[0] == MCOLS * KDIM) {
        x = (const float*)d_in[1];
        w = (const float*)d_in[0];
    }
    (void)out_size;

    cudaFuncSetAttribute(k_iter_mma, cudaFuncAttributeMaxDynamicSharedMemorySize,
                         SM_TOTAL);

    k_red<<<dim3(2, BATCH), 512>>>(x);
    k_ow<<<BATCH, 512>>>(w);

    for (int r = 0; r < 2; ++r) {
        k_iter_mma<<<dim3(NTILES, BATCH), 256, SM_TOTAL>>>(x);
        k_yred<<<dim3(2, BATCH), 512>>>();
        k_fin<<<BATCH, 512>>>(w, (r == 1) ? (float*)d_out : nullptr);
    }
}

// round 14
// speedup vs baseline: 1.1095x; 1.1095x over previous
#include <cuda_runtime.h>
#include <cuda_fp16.h>
#include <cstdint>

#define BATCH 128
#define SEQ   2048
#define KDIM  128
#define CAPS  32
#define DCAP  16
#define MCOLS 512
#define NTILES 8          // CTAs per batch; each CTA covers 256 rows
#define NPART 16          // y partial slots = tile*2 + half
#define NSUB  4           // 32-row subtiles per 128-row half

#define XST 136           // x tile stride (u16): 272B rows, ldsm conflict-free
#define PST 40            // P tile stride (u16): [n][c] layout
// smem byte offsets
#define SM_XH 0           // [2 halves][32][XST] fp16
#define SM_WH 17408       // [32][XST] fp16 hi
#define SM_WL 26112
#define SM_PH 34816       // [2 halves][32 n][PST c] fp16
#define SM_SX 39936       // softmax row-sum exchange [2][2][32] float
#define SM_TOTAL 40448

__device__ __forceinline__ uint32_t smem_u32(const void* p) {
    uint32_t a;
    asm("{ .reg .u64 t; cvta.to.shared.u64 t, %1; cvt.u32.u64 %0, t; }"
        : "=r"(a) : "l"(p));
    return a;
}
__device__ __forceinline__ void ldsm_x4(uint32_t a, uint32_t r[4]) {
    asm volatile("ldmatrix.sync.aligned.m8n8.x4.shared.b16 {%0,%1,%2,%3}, [%4];"
        : "=r"(r[0]), "=r"(r[1]), "=r"(r[2]), "=r"(r[3]) : "r"(a));
}
__device__ __forceinline__ void ldsm_x4t(uint32_t a, uint32_t r[4]) {
    asm volatile("ldmatrix.sync.aligned.m8n8.x4.trans.shared.b16 {%0,%1,%2,%3}, [%4];"
        : "=r"(r[0]), "=r"(r[1]), "=r"(r[2]), "=r"(r[3]) : "r"(a));
}
__device__ __forceinline__ void stsm_x4(uint32_t a, uint32_t r0, uint32_t r1,
                                        uint32_t r2, uint32_t r3) {
    asm volatile("stmatrix.sync.aligned.m8n8.x4.shared.b16 [%0], {%1,%2,%3,%4};"
        :: "r"(a), "r"(r0), "r"(r1), "r"(r2), "r"(r3) : "memory");
}
__device__ __forceinline__ void mma_f16(float c[4], const uint32_t a[4],
                                        uint32_t b0, uint32_t b1) {
    asm volatile("mma.sync.aligned.m16n8k16.row.col.f32.f16.f16.f32 "
        "{%0,%1,%2,%3}, {%4,%5,%6,%7}, {%8,%9}, {%0,%1,%2,%3};"
        : "+f"(c[0]), "+f"(c[1]), "+f"(c[2]), "+f"(c[3])
        : "r"(a[0]), "r"(a[1]), "r"(a[2]), "r"(a[3]), "r"(b0), "r"(b1));
}
__device__ __forceinline__ uint32_t pack_h2(__half a, __half b) {
    __half2 h = __halves2half2(a, b);
    return *(uint32_t*)&h;
}
#define BARH(id) asm volatile("bar.sync %0, 128;" :: "r"(id) : "memory")

// ---- scratch ----
__device__ uint4 g_xh4[(size_t)BATCH * SEQ * KDIM / 8];   // fp16(x), 67MB
__device__ float g_W2[BATCH][CAPS][KDIM];
__device__ unsigned short g_W2h[BATCH][CAPS * XST];
__device__ unsigned short g_W2l[BATCH][CAPS * XST];
__device__ float g_ypart[BATCH][NPART][CAPS * KDIM];

// ---- W2[b][c][k] = sum_d kernel[k, c*16+d] * o[b,c,d]; + fp16 hi/lo split ----
__device__ __forceinline__ void compute_W2(int b, int t, const float* os,
                                           const float* __restrict__ w) {
#pragma unroll
    for (int i = 0; i < 8; ++i) {
        int idx = t + i * 512;
        int c = idx >> 7, k = idx & 127;
        const float4* wr = (const float4*)(w + k * MCOLS + c * DCAP);
        const float4* ov = (const float4*)(os + c * DCAP);
        float acc = 0.f;
#pragma unroll
        for (int q = 0; q < 4; ++q) {
            float4 a = wr[q], o4 = ov[q];
            acc += a.x * o4.x + a.y * o4.y + a.z * o4.z + a.w * o4.w;
        }
        g_W2[b][c][k] = acc;
        __half hh = __float2half_rn(acc);
        __half ll = __float2half_rn(acc - __half2float(hh));
        g_W2h[b][c * XST + k] = *(unsigned short*)&hh;
        g_W2l[b][c * XST + k] = *(unsigned short*)&ll;
    }
}

// ============================================================
// Kernel 1: column sums of x + fp16(x) write + o1 + W2.
// one CTA per batch, 1024 thr.
// ============================================================
__global__ void __launch_bounds__(1024) k_init(const float* __restrict__ x,
                                               const float* __restrict__ w) {
    int b = blockIdx.x, t = threadIdx.x;
    __shared__ float4 red[32][32];
    __shared__ float S[KDIM];
    __shared__ float os[MCOLS];

    int c4 = t & 31, rg = t >> 5;
    const float4* xp = (const float4*)(x + (size_t)b * SEQ * KDIM);
    uint2* xo = (uint2*)g_xh4 + (size_t)b * SEQ * 32;
    float4 s = make_float4(0.f, 0.f, 0.f, 0.f);
#pragma unroll 4
    for (int j = 0; j < 64; ++j) {
        int row = rg + 32 * j;
        float4 v = xp[row * 32 + c4];
        s.x += v.x; s.y += v.y; s.z += v.z; s.w += v.w;
        uint2 hv;
        hv.x = pack_h2(__float2half_rn(v.x), __float2half_rn(v.y));
        hv.y = pack_h2(__float2half_rn(v.z), __float2half_rn(v.w));
        xo[row * 32 + c4] = hv;
    }
    red[rg][c4] = s;
    __syncthreads();
    if (t < KDIM) {
        int cc = t >> 2, comp = t & 3;
        float acc = 0.f;
#pragma unroll
        for (int r = 0; r < 32; ++r) acc += ((const float*)&red[r][cc])[comp];
        S[t] = acc * (1.f / 32.f);
    }
    __syncthreads();
    if (t < 512) {
        float acc = 0.f;
#pragma unroll 4
        for (int k = 0; k < KDIM; ++k) acc += S[k] * w[k * MCOLS + t];
        float sq = acc * acc;
#pragma unroll
        for (int off = 8; off >= 1; off >>= 1)
            sq += __shfl_xor_sync(0xffffffffu, sq, off, 16);
        float s2 = sq + 1e-7f;
        float scale = sqrtf(s2) / (0.5f + s2);
        os[t] = scale * acc;
    }
    __syncthreads();
    if (t < 512) compute_W2(b, t, os, w);
}

// ============================================================
// Kernel 2: routing iteration — x streamed as fp16 (half the bytes),
// phase 1 = Xh@(Wh+Wl), phase 2 = P@Xh. grid (NTILES, BATCH), 256 thr.
// ============================================================
__global__ void __launch_bounds__(256, 3) k_iter_mma() {
    extern __shared__ char sm[];
    uint32_t sb = smem_u32(sm);
    int b = blockIdx.y, tile = blockIdx.x, t = threadIdx.x;
    int wid = t >> 5, l = t & 31;
    int h = wid >> 2, wl = wid & 3;
    int barid = 1 + h;
    int ht = t & 127;

    // cooperative W tile load (all 256 threads)
    {
        const uint32_t* wh = (const uint32_t*)g_W2h[b];
        const uint32_t* wls = (const uint32_t*)g_W2l[b];
        uint32_t* swh = (uint32_t*)(sm + SM_WH);
        uint32_t* swl = (uint32_t*)(sm + SM_WL);
        for (int i = t; i < CAPS * XST / 2; i += 256) {
            swh[i] = wh[i]; swl[i] = wls[i];
        }
    }
    __syncthreads();

    uint32_t xh_base = sb + SM_XH + (uint32_t)h * 32 * XST * 2;
    uint32_t p_base  = sb + SM_PH + (uint32_t)h * 32 * PST * 2;  // [n][c]
    float* sx = (float*)(sm + SM_SX) + h * 64;

    int rh = wl & 1, ch = wl >> 1;
    int r0 = rh * 16, c0 = ch * 16;
    int cw = wl & 1, kw = wl >> 1;
    int m0c = cw * 16;

    float c2[8][4];
#pragma unroll
    for (int j = 0; j < 8; ++j)
#pragma unroll
        for (int e = 0; e < 4; ++e) c2[j][e] = 0.f;

    for (int sub = 0; sub < NSUB; ++sub) {
        BARH(barid);   // buffers free

        // ---- load 32-row fp16 x subtile (8KB per half, uint4) ----
        {
            const uint4* xb = g_xh4
                + ((size_t)(b * SEQ + tile * 256 + h * 128 + sub * 32)) * 16;
            char* xs = sm + SM_XH + h * 32 * XST * 2;
#pragma unroll
            for (int i = 0; i < 4; ++i) {
                int lin = ht + i * 128;
                int row = lin >> 4, c16 = lin & 15;
                uint4 v = xb[row * 16 + c16];
                *(uint4*)(xs + row * (XST * 2) + c16 * 16) = v;
            }
        }
        BARH(barid);   // x ready

        // ---- phase 1: logits[16n][16c] per warp = Xh @ (Wh+Wl)^T ----
        float c1[2][4];
#pragma unroll
        for (int j = 0; j < 2; ++j)
#pragma unroll
            for (int e = 0; e < 4; ++e) c1[j][e] = 0.f;

#pragma unroll
        for (int ks = 0; ks < 8; ++ks) {
            int k0 = ks * 16;
            uint32_t aaddr = xh_base + (uint32_t)(r0 + (l & 15)) * (XST * 2)
                           + k0 * 2 + (l >> 4) * 16;
            uint32_t ah[4];
            ldsm_x4(aaddr, ah);
            uint32_t baddr = sb + SM_WH
                + (uint32_t)(c0 + (l >> 4) * 8 + (l & 7)) * (XST * 2)
                + k0 * 2 + ((l >> 3) & 1) * 16;
            uint32_t bh[4], bl[4];
            ldsm_x4(baddr, bh);
            ldsm_x4(baddr + (SM_WL - SM_WH), bl);
            mma_f16(c1[0], ah, bh[0], bh[1]);
            mma_f16(c1[1], ah, bh[2], bh[3]);
            mma_f16(c1[0], ah, bl[0], bl[1]);
            mma_f16(c1[1], ah, bl[2], bl[3]);
        }

        // ---- softmax (no-max; exact-math identical): exp + cross-warp sums ----
        {
#pragma unroll
            for (int j = 0; j < 2; ++j)
#pragma unroll
                for (int e = 0; e < 4; ++e) c1[j][e] = __expf(c1[j][e]);
            float s0 = c1[0][0] + c1[0][1] + c1[1][0] + c1[1][1];
            float s1 = c1[0][2] + c1[0][3] + c1[1][2] + c1[1][3];
            s0 += __shfl_xor_sync(0xffffffffu, s0, 1);
            s0 += __shfl_xor_sync(0xffffffffu, s0, 2);
            s1 += __shfl_xor_sync(0xffffffffu, s1, 1);
            s1 += __shfl_xor_sync(0xffffffffu, s1, 2);
            if ((l & 3) == 0) {
                sx[ch * 32 + r0 + (l >> 2)]     = s0;
                sx[ch * 32 + r0 + (l >> 2) + 8] = s1;
            }
        }
        BARH(barid);   // sums ready

        // ---- finish softmax + write P[n][c] via one stmatrix.x4 ----
        {
            int nr = r0 + (l >> 2);
            float inv0 = 1.f / (sx[nr] + sx[32 + nr]);
            float inv1 = 1.f / (sx[nr + 8] + sx[32 + nr + 8]);
            uint32_t d0 = pack_h2(__float2half_rn(c1[0][0] * inv0),
                                  __float2half_rn(c1[0][1] * inv0));
            uint32_t d1 = pack_h2(__float2half_rn(c1[1][0] * inv0),
                                  __float2half_rn(c1[1][1] * inv0));
            uint32_t d2 = pack_h2(__float2half_rn(c1[0][2] * inv1),
                                  __float2half_rn(c1[0][3] * inv1));
            uint32_t d3 = pack_h2(__float2half_rn(c1[1][2] * inv1),
                                  __float2half_rn(c1[1][3] * inv1));
            uint32_t addr = p_base
                + (uint32_t)(r0 + ((l >> 4) & 1) * 8 + (l & 7)) * (PST * 2)
                + (c0 + ((l >> 3) & 1) * 8) * 2;
            stsm_x4(addr, d0, d1, d2, d3);
        }
        BARH(barid);   // P ready

        // ---- phase 2: Y^T[16c][64k per warp] += P^T @ Xh (1 combo) ----
#pragma unroll
        for (int ns = 0; ns < 2; ++ns) {
            int n0 = ns * 16;
            uint32_t aaddr = p_base
                + (uint32_t)(n0 + ((l >> 4) & 1) * 8 + (l & 7)) * (PST * 2)
                + (m0c + ((l >> 3) & 1) * 8) * 2;
            uint32_t ah[4];
            ldsm_x4t(aaddr, ah);
#pragma unroll
            for (int q = 0; q < 4; ++q) {
                int k0 = kw * 64 + q * 16;
                uint32_t baddr = xh_base
                    + (uint32_t)(n0 + (l & 15)) * (XST * 2)
                    + (k0 + 8 * (l >> 4)) * 2;
                uint32_t bh[4];
                ldsm_x4t(baddr, bh);
                mma_f16(c2[2 * q],     ah, bh[0], bh[1]);
                mma_f16(c2[2 * q + 1], ah, bh[2], bh[3]);
            }
        }
    }

    // ---- write y partial: slot = tile*2 + h ----
    {
        float* yo = &g_ypart[b][tile * 2 + h][0];
        int cr = m0c + (l >> 2);
#pragma unroll
        for (int q = 0; q < 4; ++q) {
            int k = kw * 64 + q * 16 + (l & 3) * 2;
            yo[cr * KDIM + k]            = c2[2 * q][0];
            yo[cr * KDIM + k + 1]        = c2[2 * q][1];
            yo[(cr + 8) * KDIM + k]      = c2[2 * q][2];
            yo[(cr + 8) * KDIM + k + 1]  = c2[2 * q][3];
            yo[cr * KDIM + k + 8]        = c2[2 * q + 1][0];
            yo[cr * KDIM + k + 9]        = c2[2 * q + 1][1];
            yo[(cr + 8) * KDIM + k + 8]  = c2[2 * q + 1][2];
            yo[(cr + 8) * KDIM + k + 9]  = c2[2 * q + 1][3];
        }
    }
}

// ============================================================
// Kernel 3: sum 16 y partials, u = y @ kernel, squash; output or fused W2.
// grid 128, 512 thr.
// ============================================================
__global__ void k_fin(const float* __restrict__ w, float* __restrict__ out) {
    int b = blockIdx.x, t = threadIdx.x;
    __shared__ float ys[CAPS * KDIM];
    __shared__ float os[MCOLS];
#pragma unroll
    for (int i = 0; i < 8; ++i) {
        int idx = t + i * 512;
        float s = 0.f;
#pragma unroll
        for (int p = 0; p < NPART; ++p) s += g_ypart[b][p][idx];
        ys[idx] = s;
    }
    __syncthreads();
    int c = t >> 4;
    const float* yr = &ys[c * KDIM];
    float acc = 0.f;
#pragma unroll 8
    for (int k = 0; k < KDIM; ++k) acc += yr[k] * w[k * MCOLS + t];
    float sq = acc * acc;
#pragma unroll
    for (int off = 8; off >= 1; off >>= 1)
        sq += __shfl_xor_sync(0xffffffffu, sq, off, 16);
    float s2 = sq + 1e-7f;
    float scale = sqrtf(s2) / (0.5f + s2);
    float val = scale * acc;
    if (out) {
        out[b * MCOLS + t] = val;
    } else {
        os[t] = val;
        __syncthreads();
        compute_W2(b, t, os, w);
    }
}

extern "C" void kernel_launch(void* const* d_in, const int* in_sizes, int n_in,
                              void* d_out, int out_size) {
    const float* x = (const float*)d_in[0];
    const float* w = (const float*)d_in[1];
    if (n_in >= 2 && in_sizes[0] == MCOLS * KDIM) {
        x = (const float*)d_in[1];
        w = (const float*)d_in[0];
    }
    (void)out_size;

    cudaFuncSetAttribute(k_iter_mma, cudaFuncAttributeMaxDynamicSharedMemorySize,
                         SM_TOTAL);

    k_init<<<BATCH, 1024>>>(x, w);

    for (int r = 0; r < 2; ++r) {
        k_iter_mma<<<dim3(NTILES, BATCH), 256, SM_TOTAL>>>();
        k_fin<<<BATCH, 512>>>(w, (r == 1) ? (float*)d_out : nullptr);
    }
}

// round 16
// speedup vs baseline: 1.1723x; 1.0566x over previous
#include <cuda_runtime.h>
#include <cuda_fp16.h>
#include <cstdint>

#define BATCH 128
#define SEQ   2048
#define KDIM  128
#define CAPS  32
#define DCAP  16
#define MCOLS 512
#define NTILES 8          // CTAs per batch; each CTA covers 256 rows
#define NPART 16          // y partial slots = tile*2 + half
#define NSUB  2           // 64-row subtiles per 128-row half

#define XST 136           // x tile stride (u16): 272B rows, ldsm conflict-free
#define PST 40            // P tile stride (u16): [n][c] layout
// smem byte offsets
#define SM_XH 0           // [2 halves][64][XST] fp16
#define SM_WH 34816       // [32][XST] fp16 hi
#define SM_WL 43520
#define SM_PH 52224       // [2 halves][64 n][PST c] fp16
#define SM_TOTAL 62464

__device__ __forceinline__ uint32_t smem_u32(const void* p) {
    uint32_t a;
    asm("{ .reg .u64 t; cvta.to.shared.u64 t, %1; cvt.u32.u64 %0, t; }"
        : "=r"(a) : "l"(p));
    return a;
}
__device__ __forceinline__ void ldsm_x4(uint32_t a, uint32_t r[4]) {
    asm volatile("ldmatrix.sync.aligned.m8n8.x4.shared.b16 {%0,%1,%2,%3}, [%4];"
        : "=r"(r[0]), "=r"(r[1]), "=r"(r[2]), "=r"(r[3]) : "r"(a));
}
__device__ __forceinline__ void ldsm_x4t(uint32_t a, uint32_t r[4]) {
    asm volatile("ldmatrix.sync.aligned.m8n8.x4.trans.shared.b16 {%0,%1,%2,%3}, [%4];"
        : "=r"(r[0]), "=r"(r[1]), "=r"(r[2]), "=r"(r[3]) : "r"(a));
}
__device__ __forceinline__ void stsm_x4(uint32_t a, uint32_t r0, uint32_t r1,
                                        uint32_t r2, uint32_t r3) {
    asm volatile("stmatrix.sync.aligned.m8n8.x4.shared.b16 [%0], {%1,%2,%3,%4};"
        :: "r"(a), "r"(r0), "r"(r1), "r"(r2), "r"(r3) : "memory");
}
__device__ __forceinline__ void mma_f16(float c[4], const uint32_t a[4],
                                        uint32_t b0, uint32_t b1) {
    asm volatile("mma.sync.aligned.m16n8k16.row.col.f32.f16.f16.f32 "
        "{%0,%1,%2,%3}, {%4,%5,%6,%7}, {%8,%9}, {%0,%1,%2,%3};"
        : "+f"(c[0]), "+f"(c[1]), "+f"(c[2]), "+f"(c[3])
        : "r"(a[0]), "r"(a[1]), "r"(a[2]), "r"(a[3]), "r"(b0), "r"(b1));
}
__device__ __forceinline__ uint32_t pack_h2(__half a, __half b) {
    __half2 h = __halves2half2(a, b);
    return *(uint32_t*)&h;
}
#define BARH(id) asm volatile("bar.sync %0, 128;" :: "r"(id) : "memory")

// ---- scratch ----
__device__ uint4 g_xh4[(size_t)BATCH * SEQ * KDIM / 8];   // fp16(x), 67MB
__device__ float g_S2[BATCH][2][KDIM];
__device__ float g_W2[BATCH][CAPS][KDIM];
__device__ unsigned short g_W2h[BATCH][CAPS * XST];
__device__ unsigned short g_W2l[BATCH][CAPS * XST];
__device__ float g_ypart[BATCH][NPART][CAPS * KDIM];

// ---- W2[b][c][k] = sum_d kernel[k, c*16+d] * o[b,c,d]; + fp16 hi/lo split ----
__device__ __forceinline__ void compute_W2(int b, int t, const float* os,
                                           const float* __restrict__ w) {
#pragma unroll
    for (int i = 0; i < 8; ++i) {
        int idx = t + i * 512;
        int c = idx >> 7, k = idx & 127;
        const float4* wr = (const float4*)(w + k * MCOLS + c * DCAP);
        const float4* ov = (const float4*)(os + c * DCAP);
        float acc = 0.f;
#pragma unroll
        for (int q = 0; q < 4; ++q) {
            float4 a = wr[q], o4 = ov[q];
            acc += a.x * o4.x + a.y * o4.y + a.z * o4.z + a.w * o4.w;
        }
        g_W2[b][c][k] = acc;
        __half hh = __float2half_rn(acc);
        __half ll = __float2half_rn(acc - __half2float(hh));
        g_W2h[b][c * XST + k] = *(unsigned short*)&hh;
        g_W2l[b][c * XST + k] = *(unsigned short*)&ll;
    }
}

// ============================================================
// Kernel 1a: convert x->fp16 + partial column sums. grid (2, BATCH), 512 thr.
// ============================================================
__global__ void __launch_bounds__(512) k_conv(const float* __restrict__ x) {
    int b = blockIdx.y, half = blockIdx.x, t = threadIdx.x;
    __shared__ float4 red[16][32];
    int c4 = t & 31, rg = t >> 5;
    const float4* xp = (const float4*)(x + ((size_t)b * SEQ + half * 1024) * KDIM);
    uint2* xo = (uint2*)g_xh4 + ((size_t)b * SEQ + half * 1024) * 32;
    float4 s = make_float4(0.f, 0.f, 0.f, 0.f);
#pragma unroll 4
    for (int j = 0; j < 64; ++j) {
        int row = rg + 16 * j;
        float4 v = xp[row * 32 + c4];
        s.x += v.x; s.y += v.y; s.z += v.z; s.w += v.w;
        uint2 hv;
        hv.x = pack_h2(__float2half_rn(v.x), __float2half_rn(v.y));
        hv.y = pack_h2(__float2half_rn(v.z), __float2half_rn(v.w));
        xo[row * 32 + c4] = hv;
    }
    red[rg][c4] = s;
    __syncthreads();
    if (t < 32) {
        float4 a = red[0][t];
#pragma unroll
        for (int r = 1; r < 16; ++r) {
            float4 v = red[r][t];
            a.x += v.x; a.y += v.y; a.z += v.z; a.w += v.w;
        }
        *(float4*)&g_S2[b][half][t * 4] = a;
    }
}

// ============================================================
// Kernel 1b: o1 = squash((1/32)*S@kernel) + fused W2. grid 128, 512 thr.
// ============================================================
__global__ void k_ow(const float* __restrict__ w) {
    int b = blockIdx.x, t = threadIdx.x;
    __shared__ float S[KDIM];
    __shared__ float os[MCOLS];
    if (t < KDIM)
        S[t] = (g_S2[b][0][t] + g_S2[b][1][t]) * (1.f / 32.f);
    __syncthreads();
    float acc = 0.f;
#pragma unroll 4
    for (int k = 0; k < KDIM; ++k) acc += S[k] * w[k * MCOLS + t];
    float sq = acc * acc;
#pragma unroll
    for (int off = 8; off >= 1; off >>= 1)
        sq += __shfl_xor_sync(0xffffffffu, sq, off, 16);
    float s2 = sq + 1e-7f;
    float scale = sqrtf(s2) / (0.5f + s2);
    os[t] = scale * acc;
    __syncthreads();
    compute_W2(b, t, os, w);
}

// ============================================================
// Kernel 2: routing iteration — 64-row subtiles, register prefetch,
// warp-local softmax. grid (NTILES, BATCH), 256 thr.
// ============================================================
__global__ void __launch_bounds__(256) k_iter_mma() {
    extern __shared__ char sm[];
    uint32_t sb = smem_u32(sm);
    int b = blockIdx.y, tile = blockIdx.x, t = threadIdx.x;
    int wid = t >> 5, l = t & 31;
    int h = wid >> 2, wl = wid & 3;
    int barid = 1 + h;
    int ht = t & 127;

    // cooperative W tile load (all 256 threads)
    {
        const uint32_t* wh = (const uint32_t*)g_W2h[b];
        const uint32_t* wls = (const uint32_t*)g_W2l[b];
        uint32_t* swh = (uint32_t*)(sm + SM_WH);
        uint32_t* swl = (uint32_t*)(sm + SM_WL);
        for (int i = t; i < CAPS * XST / 2; i += 256) {
            swh[i] = wh[i]; swl[i] = wls[i];
        }
    }

    uint32_t xh_base = sb + SM_XH + (uint32_t)h * 64 * XST * 2;
    uint32_t p_base  = sb + SM_PH + (uint32_t)h * 64 * PST * 2;  // [n][c]

    // phase-1: warp owns rows wl*16..+16, ALL 32 capsules
    int r0 = wl * 16;
    // phase-2: caps (wl&1)*16, k (wl>>1)*64
    int cw = wl & 1, kw = wl >> 1;
    int m0c = cw * 16;

    float c2[8][4];
#pragma unroll
    for (int j = 0; j < 8; ++j)
#pragma unroll
        for (int e = 0; e < 4; ++e) c2[j][e] = 0.f;

    const uint4* xg = g_xh4 + ((size_t)(b * SEQ + tile * 256 + h * 128)) * 16;
    uint4 pf[8];
    // prefetch subtile 0
#pragma unroll
    for (int i = 0; i < 8; ++i) pf[i] = xg[ht + i * 128];
    __syncthreads();   // W ready

    for (int sub = 0; sub < NSUB; ++sub) {
        BARH(barid);   // xs & P free (prev subtile fully consumed)

        // ---- store prefetched x subtile to smem ----
        {
            char* xs = sm + SM_XH + h * 64 * XST * 2;
#pragma unroll
            for (int i = 0; i < 8; ++i) {
                int lin = ht + i * 128;
                int row = lin >> 4, c16 = lin & 15;
                *(uint4*)(xs + row * (XST * 2) + c16 * 16) = pf[i];
            }
        }
        BARH(barid);   // x ready

        // ---- prefetch next subtile (overlaps all compute below) ----
        if (sub + 1 < NSUB) {
            const uint4* xn = xg + (size_t)(sub + 1) * 64 * 16;
#pragma unroll
            for (int i = 0; i < 8; ++i) pf[i] = xn[ht + i * 128];
        }

        // ---- phase 1: logits[16n][32c] per warp = Xh @ (Wh+Wl)^T ----
        float c1[4][4];
#pragma unroll
        for (int j = 0; j < 4; ++j)
#pragma unroll
            for (int e = 0; e < 4; ++e) c1[j][e] = 0.f;

#pragma unroll
        for (int ks = 0; ks < 8; ++ks) {
            int k0 = ks * 16;
            uint32_t aaddr = xh_base + (uint32_t)(r0 + (l & 15)) * (XST * 2)
                           + k0 * 2 + (l >> 4) * 16;
            uint32_t ah[4];
            ldsm_x4(aaddr, ah);
            uint32_t wrow = (uint32_t)((l >> 4) * 8 + (l & 7)) * (XST * 2)
                          + k0 * 2 + ((l >> 3) & 1) * 16;
            uint32_t bh0[4], bh1[4], bl0[4], bl1[4];
            ldsm_x4(sb + SM_WH + wrow, bh0);
            ldsm_x4(sb + SM_WH + 16 * (XST * 2) + wrow, bh1);
            ldsm_x4(sb + SM_WL + wrow, bl0);
            ldsm_x4(sb + SM_WL + 16 * (XST * 2) + wrow, bl1);
            mma_f16(c1[0], ah, bh0[0], bh0[1]);
            mma_f16(c1[1], ah, bh0[2], bh0[3]);
            mma_f16(c1[2], ah, bh1[0], bh1[1]);
            mma_f16(c1[3], ah, bh1[2], bh1[3]);
            mma_f16(c1[0], ah, bl0[0], bl0[1]);
            mma_f16(c1[1], ah, bl0[2], bl0[3]);
            mma_f16(c1[2], ah, bl1[0], bl1[1]);
            mma_f16(c1[3], ah, bl1[2], bl1[3]);
        }

        // ---- warp-local softmax (no-max; exact-math identical) ----
        {
#pragma unroll
            for (int j = 0; j < 4; ++j)
#pragma unroll
                for (int e = 0; e < 4; ++e) c1[j][e] = __expf(c1[j][e]);
            float s0 = 0.f, s1 = 0.f;
#pragma unroll
            for (int j = 0; j < 4; ++j) {
                s0 += c1[j][0] + c1[j][1];
                s1 += c1[j][2] + c1[j][3];
            }
            s0 += __shfl_xor_sync(0xffffffffu, s0, 1);
            s0 += __shfl_xor_sync(0xffffffffu, s0, 2);
            s1 += __shfl_xor_sync(0xffffffffu, s1, 1);
            s1 += __shfl_xor_sync(0xffffffffu, s1, 2);
            float inv0 = 1.f / s0, inv1 = 1.f / s1;

            // write P[n][c] via two stmatrix.x4 (16 rows x 32 cols).
            // Octet address pattern: m0=(r0,c0) m1=(r0,c+8) m2=(r+8,c0) m3=(r+8,c+8)
            // => register order must be (g_even rows0, g_odd rows0,
            //                            g_even rows8, g_odd rows8).
            uint32_t addr0 = p_base
                + (uint32_t)(r0 + ((l >> 4) & 1) * 8 + (l & 7)) * (PST * 2)
                + (((l >> 3) & 1) * 8) * 2;
            stsm_x4(addr0,
                    pack_h2(__float2half_rn(c1[0][0] * inv0),
                            __float2half_rn(c1[0][1] * inv0)),
                    pack_h2(__float2half_rn(c1[1][0] * inv0),
                            __float2half_rn(c1[1][1] * inv0)),
                    pack_h2(__float2half_rn(c1[0][2] * inv1),
                            __float2half_rn(c1[0][3] * inv1)),
                    pack_h2(__float2half_rn(c1[1][2] * inv1),
                            __float2half_rn(c1[1][3] * inv1)));
            stsm_x4(addr0 + 32,
                    pack_h2(__float2half_rn(c1[2][0] * inv0),
                            __float2half_rn(c1[2][1] * inv0)),
                    pack_h2(__float2half_rn(c1[3][0] * inv0),
                            __float2half_rn(c1[3][1] * inv0)),
                    pack_h2(__float2half_rn(c1[2][2] * inv1),
                            __float2half_rn(c1[2][3] * inv1)),
                    pack_h2(__float2half_rn(c1[3][2] * inv1),
                            __float2half_rn(c1[3][3] * inv1)));
        }
        BARH(barid);   // P ready

        // ---- phase 2: Y^T[16c][64k per warp] += P^T @ Xh ----
#pragma unroll
        for (int ns = 0; ns < 4; ++ns) {
            int n0 = ns * 16;
            uint32_t aaddr = p_base
                + (uint32_t)(n0 + ((l >> 4) & 1) * 8 + (l & 7)) * (PST * 2)
                + (m0c + ((l >> 3) & 1) * 8) * 2;
            uint32_t ah[4];
            ldsm_x4t(aaddr, ah);
#pragma unroll
            for (int q = 0; q < 4; ++q) {
                int k0 = kw * 64 + q * 16;
                uint32_t baddr = xh_base
                    + (uint32_t)(n0 + (l & 15)) * (XST * 2)
                    + (k0 + 8 * (l >> 4)) * 2;
                uint32_t bh[4];
                ldsm_x4t(baddr, bh);
                mma_f16(c2[2 * q],     ah, bh[0], bh[1]);
                mma_f16(c2[2 * q + 1], ah, bh[2], bh[3]);
            }
        }
    }

    // ---- write y partial: slot = tile*2 + h ----
    {
        float* yo = &g_ypart[b][tile * 2 + h][0];
        int cr = m0c + (l >> 2);
#pragma unroll
        for (int q = 0; q < 4; ++q) {
            int k = kw * 64 + q * 16 + (l & 3) * 2;
            yo[cr * KDIM + k]            = c2[2 * q][0];
            yo[cr * KDIM + k + 1]        = c2[2 * q][1];
            yo[(cr + 8) * KDIM + k]      = c2[2 * q][2];
            yo[(cr + 8) * KDIM + k + 1]  = c2[2 * q][3];
            yo[cr * KDIM + k + 8]        = c2[2 * q + 1][0];
            yo[cr * KDIM + k + 9]        = c2[2 * q + 1][1];
            yo[(cr + 8) * KDIM + k + 8]  = c2[2 * q + 1][2];
            yo[(cr + 8) * KDIM + k + 9]  = c2[2 * q + 1][3];
        }
    }
}

// ============================================================
// Kernel 3: sum 16 y partials, u = y @ kernel, squash; output or fused W2.
// grid 128, 512 thr.
// ============================================================
__global__ void k_fin(const float* __restrict__ w, float* __restrict__ out) {
    int b = blockIdx.x, t = threadIdx.x;
    __shared__ float ys[CAPS * KDIM];
    __shared__ float os[MCOLS];
#pragma unroll
    for (int i = 0; i < 8; ++i) {
        int idx = t + i * 512;
        float s = 0.f;
#pragma unroll
        for (int p = 0; p < NPART; ++p) s += g_ypart[b][p][idx];
        ys[idx] = s;
    }
    __syncthreads();
    int c = t >> 4;
    const float* yr = &ys[c * KDIM];
    float acc = 0.f;
#pragma unroll 8
    for (int k = 0; k < KDIM; ++k) acc += yr[k] * w[k * MCOLS + t];
    float sq = acc * acc;
#pragma unroll
    for (int off = 8; off >= 1; off >>= 1)
        sq += __shfl_xor_sync(0xffffffffu, sq, off, 16);
    float s2 = sq + 1e-7f;
    float scale = sqrtf(s2) / (0.5f + s2);
    float val = scale * acc;
    if (out) {
        out[b * MCOLS + t] = val;
    } else {
        os[t] = val;
        __syncthreads();
        compute_W2(b, t, os, w);
    }
}

extern "C" void kernel_launch(void* const* d_in, const int* in_sizes, int n_in,
                              void* d_out, int out_size) {
    const float* x = (const float*)d_in[0];
    const float* w = (const float*)d_in[1];
    if (n_in >= 2 && in_sizes[0] == MCOLS * KDIM) {
        x = (const float*)d_in[1];
        w = (const float*)d_in[0];
    }
    (void)out_size;

    cudaFuncSetAttribute(k_iter_mma, cudaFuncAttributeMaxDynamicSharedMemorySize,
                         SM_TOTAL);

    k_conv<<<dim3(2, BATCH), 512>>>(x);
    k_ow<<<BATCH, 512>>>(w);

    for (int r = 0; r < 2; ++r) {
        k_iter_mma<<<dim3(NTILES, BATCH), 256, SM_TOTAL>>>();
        k_fin<<<BATCH, 512>>>(w, (r == 1) ? (float*)d_out : nullptr);
    }
}

// round 17
// speedup vs baseline: 1.1725x; 1.0002x over previous
#include <cuda_runtime.h>
#include <cuda_fp16.h>
#include <cstdint>

#define BATCH 128
#define SEQ   2048
#define KDIM  128
#define CAPS  32
#define DCAP  16
#define MCOLS 512
#define NTILES 8          // CTAs per batch; each CTA covers 256 rows
#define NPART 16          // y partial slots = tile*2 + half
#define NSUB  2           // 64-row subtiles per 128-row half

#define XST 136           // x tile stride (u16): 272B rows, ldsm conflict-free
#define PST 40            // P tile stride (u16): [n][c] layout
// smem byte offsets
#define SM_XH 0           // [2 halves][64][XST] fp16
#define SM_WH 34816       // [32][XST] fp16 hi
#define SM_WL 43520
#define SM_PH 52224       // [2 halves][64 n][PST c] fp16
#define SM_TOTAL 62464

__device__ __forceinline__ uint32_t smem_u32(const void* p) {
    uint32_t a;
    asm("{ .reg .u64 t; cvta.to.shared.u64 t, %1; cvt.u32.u64 %0, t; }"
        : "=r"(a) : "l"(p));
    return a;
}
__device__ __forceinline__ void ldsm_x4(uint32_t a, uint32_t r[4]) {
    asm volatile("ldmatrix.sync.aligned.m8n8.x4.shared.b16 {%0,%1,%2,%3}, [%4];"
        : "=r"(r[0]), "=r"(r[1]), "=r"(r[2]), "=r"(r[3]) : "r"(a));
}
__device__ __forceinline__ void ldsm_x4t(uint32_t a, uint32_t r[4]) {
    asm volatile("ldmatrix.sync.aligned.m8n8.x4.trans.shared.b16 {%0,%1,%2,%3}, [%4];"
        : "=r"(r[0]), "=r"(r[1]), "=r"(r[2]), "=r"(r[3]) : "r"(a));
}
__device__ __forceinline__ void stsm_x4(uint32_t a, uint32_t r0, uint32_t r1,
                                        uint32_t r2, uint32_t r3) {
    asm volatile("stmatrix.sync.aligned.m8n8.x4.shared.b16 [%0], {%1,%2,%3,%4};"
        :: "r"(a), "r"(r0), "r"(r1), "r"(r2), "r"(r3) : "memory");
}
__device__ __forceinline__ void mma_f16(float c[4], const uint32_t a[4],
                                        uint32_t b0, uint32_t b1) {
    asm volatile("mma.sync.aligned.m16n8k16.row.col.f32.f16.f16.f32 "
        "{%0,%1,%2,%3}, {%4,%5,%6,%7}, {%8,%9}, {%0,%1,%2,%3};"
        : "+f"(c[0]), "+f"(c[1]), "+f"(c[2]), "+f"(c[3])
        : "r"(a[0]), "r"(a[1]), "r"(a[2]), "r"(a[3]), "r"(b0), "r"(b1));
}
__device__ __forceinline__ uint32_t pack_h2(__half a, __half b) {
    __half2 h = __halves2half2(a, b);
    return *(uint32_t*)&h;
}
#define BARH(id) asm volatile("bar.sync %0, 128;" :: "r"(id) : "memory")

// ---- scratch ----
__device__ uint4 g_xh4[(size_t)BATCH * SEQ * KDIM / 8];   // fp16(x), 67MB
__device__ float g_S2[BATCH][2][KDIM];
__device__ unsigned short g_W2h[BATCH][CAPS * XST];
__device__ unsigned short g_W2l[BATCH][CAPS * XST];
__device__ float g_ypart[BATCH][NPART][CAPS * KDIM];

// ---- W2[b][c][k] = sum_d kernel[k, c*16+d] * o[b,c,d]; fp16 hi/lo split ----
// full-batch version (used by k_ow; t in [0,512))
__device__ __forceinline__ void compute_W2(int b, int t, const float* os,
                                           const float* __restrict__ w) {
#pragma unroll
    for (int i = 0; i < 8; ++i) {
        int idx = t + i * 512;
        int c = idx >> 7, k = idx & 127;
        const float4* wr = (const float4*)(w + k * MCOLS + c * DCAP);
        const float4* ov = (const float4*)(os + c * DCAP);
        float acc = 0.f;
#pragma unroll
        for (int q = 0; q < 4; ++q) {
            float4 a = wr[q], o4 = ov[q];
            acc += a.x * o4.x + a.y * o4.y + a.z * o4.z + a.w * o4.w;
        }
        __half hh = __float2half_rn(acc);
        __half ll = __float2half_rn(acc - __half2float(hh));
        g_W2h[b][c * XST + k] = *(unsigned short*)&hh;
        g_W2l[b][c * XST + k] = *(unsigned short*)&ll;
    }
}

// ============================================================
// Kernel 1a: convert x->fp16 + partial column sums. grid (2, BATCH), 512 thr.
// ============================================================
__global__ void __launch_bounds__(512) k_conv(const float* __restrict__ x) {
    int b = blockIdx.y, half = blockIdx.x, t = threadIdx.x;
    __shared__ float4 red[16][32];
    int c4 = t & 31, rg = t >> 5;
    const float4* xp = (const float4*)(x + ((size_t)b * SEQ + half * 1024) * KDIM);
    uint2* xo = (uint2*)g_xh4 + ((size_t)b * SEQ + half * 1024) * 32;
    float4 s = make_float4(0.f, 0.f, 0.f, 0.f);
#pragma unroll 4
    for (int j = 0; j < 64; ++j) {
        int row = rg + 16 * j;
        float4 v = xp[row * 32 + c4];
        s.x += v.x; s.y += v.y; s.z += v.z; s.w += v.w;
        uint2 hv;
        hv.x = pack_h2(__float2half_rn(v.x), __float2half_rn(v.y));
        hv.y = pack_h2(__float2half_rn(v.z), __float2half_rn(v.w));
        xo[row * 32 + c4] = hv;
    }
    red[rg][c4] = s;
    __syncthreads();
    if (t < 32) {
        float4 a = red[0][t];
#pragma unroll
        for (int r = 1; r < 16; ++r) {
            float4 v = red[r][t];
            a.x += v.x; a.y += v.y; a.z += v.z; a.w += v.w;
        }
        *(float4*)&g_S2[b][half][t * 4] = a;
    }
}

// ============================================================
// Kernel 1b: o1 = squash((1/32)*S@kernel) + fused W2. grid 128, 512 thr.
// ============================================================
__global__ void k_ow(const float* __restrict__ w) {
    int b = blockIdx.x, t = threadIdx.x;
    __shared__ float S[KDIM];
    __shared__ float os[MCOLS];
    if (t < KDIM)
        S[t] = (g_S2[b][0][t] + g_S2[b][1][t]) * (1.f / 32.f);
    __syncthreads();
    float acc = 0.f;
#pragma unroll 4
    for (int k = 0; k < KDIM; ++k) acc += S[k] * w[k * MCOLS + t];
    float sq = acc * acc;
#pragma unroll
    for (int off = 8; off >= 1; off >>= 1)
        sq += __shfl_xor_sync(0xffffffffu, sq, off, 16);
    float s2 = sq + 1e-7f;
    float scale = sqrtf(s2) / (0.5f + s2);
    os[t] = scale * acc;
    __syncthreads();
    compute_W2(b, t, os, w);
}

// ============================================================
// Kernel 2: routing iteration — 64-row subtiles, register prefetch,
// warp-local softmax. grid (NTILES, BATCH), 256 thr.  (unchanged from R16)
// ============================================================
__global__ void __launch_bounds__(256) k_iter_mma() {
    extern __shared__ char sm[];
    uint32_t sb = smem_u32(sm);
    int b = blockIdx.y, tile = blockIdx.x, t = threadIdx.x;
    int wid = t >> 5, l = t & 31;
    int h = wid >> 2, wl = wid & 3;
    int barid = 1 + h;
    int ht = t & 127;

    {
        const uint32_t* wh = (const uint32_t*)g_W2h[b];
        const uint32_t* wls = (const uint32_t*)g_W2l[b];
        uint32_t* swh = (uint32_t*)(sm + SM_WH);
        uint32_t* swl = (uint32_t*)(sm + SM_WL);
        for (int i = t; i < CAPS * XST / 2; i += 256) {
            swh[i] = wh[i]; swl[i] = wls[i];
        }
    }

    uint32_t xh_base = sb + SM_XH + (uint32_t)h * 64 * XST * 2;
    uint32_t p_base  = sb + SM_PH + (uint32_t)h * 64 * PST * 2;

    int r0 = wl * 16;
    int cw = wl & 1, kw = wl >> 1;
    int m0c = cw * 16;

    float c2[8][4];
#pragma unroll
    for (int j = 0; j < 8; ++j)
#pragma unroll
        for (int e = 0; e < 4; ++e) c2[j][e] = 0.f;

    const uint4* xg = g_xh4 + ((size_t)(b * SEQ + tile * 256 + h * 128)) * 16;
    uint4 pf[8];
#pragma unroll
    for (int i = 0; i < 8; ++i) pf[i] = xg[ht + i * 128];
    __syncthreads();   // W ready

    for (int sub = 0; sub < NSUB; ++sub) {
        BARH(barid);
        {
            char* xs = sm + SM_XH + h * 64 * XST * 2;
#pragma unroll
            for (int i = 0; i < 8; ++i) {
                int lin = ht + i * 128;
                int row = lin >> 4, c16 = lin & 15;
                *(uint4*)(xs + row * (XST * 2) + c16 * 16) = pf[i];
            }
        }
        BARH(barid);
        if (sub + 1 < NSUB) {
            const uint4* xn = xg + (size_t)(sub + 1) * 64 * 16;
#pragma unroll
            for (int i = 0; i < 8; ++i) pf[i] = xn[ht + i * 128];
        }

        float c1[4][4];
#pragma unroll
        for (int j = 0; j < 4; ++j)
#pragma unroll
            for (int e = 0; e < 4; ++e) c1[j][e] = 0.f;

#pragma unroll
        for (int ks = 0; ks < 8; ++ks) {
            int k0 = ks * 16;
            uint32_t aaddr = xh_base + (uint32_t)(r0 + (l & 15)) * (XST * 2)
                           + k0 * 2 + (l >> 4) * 16;
            uint32_t ah[4];
            ldsm_x4(aaddr, ah);
            uint32_t wrow = (uint32_t)((l >> 4) * 8 + (l & 7)) * (XST * 2)
                          + k0 * 2 + ((l >> 3) & 1) * 16;
            uint32_t bh0[4], bh1[4], bl0[4], bl1[4];
            ldsm_x4(sb + SM_WH + wrow, bh0);
            ldsm_x4(sb + SM_WH + 16 * (XST * 2) + wrow, bh1);
            ldsm_x4(sb + SM_WL + wrow, bl0);
            ldsm_x4(sb + SM_WL + 16 * (XST * 2) + wrow, bl1);
            mma_f16(c1[0], ah, bh0[0], bh0[1]);
            mma_f16(c1[1], ah, bh0[2], bh0[3]);
            mma_f16(c1[2], ah, bh1[0], bh1[1]);
            mma_f16(c1[3], ah, bh1[2], bh1[3]);
            mma_f16(c1[0], ah, bl0[0], bl0[1]);
            mma_f16(c1[1], ah, bl0[2], bl0[3]);
            mma_f16(c1[2], ah, bl1[0], bl1[1]);
            mma_f16(c1[3], ah, bl1[2], bl1[3]);
        }

        {
#pragma unroll
            for (int j = 0; j < 4; ++j)
#pragma unroll
                for (int e = 0; e < 4; ++e) c1[j][e] = __expf(c1[j][e]);
            float s0 = 0.f, s1 = 0.f;
#pragma unroll
            for (int j = 0; j < 4; ++j) {
                s0 += c1[j][0] + c1[j][1];
                s1 += c1[j][2] + c1[j][3];
            }
            s0 += __shfl_xor_sync(0xffffffffu, s0, 1);
            s0 += __shfl_xor_sync(0xffffffffu, s0, 2);
            s1 += __shfl_xor_sync(0xffffffffu, s1, 1);
            s1 += __shfl_xor_sync(0xffffffffu, s1, 2);
            float inv0 = 1.f / s0, inv1 = 1.f / s1;

            uint32_t addr0 = p_base
                + (uint32_t)(r0 + ((l >> 4) & 1) * 8 + (l & 7)) * (PST * 2)
                + (((l >> 3) & 1) * 8) * 2;
            stsm_x4(addr0,
                    pack_h2(__float2half_rn(c1[0][0] * inv0),
                            __float2half_rn(c1[0][1] * inv0)),
                    pack_h2(__float2half_rn(c1[1][0] * inv0),
                            __float2half_rn(c1[1][1] * inv0)),
                    pack_h2(__float2half_rn(c1[0][2] * inv1),
                            __float2half_rn(c1[0][3] * inv1)),
                    pack_h2(__float2half_rn(c1[1][2] * inv1),
                            __float2half_rn(c1[1][3] * inv1)));
            stsm_x4(addr0 + 32,
                    pack_h2(__float2half_rn(c1[2][0] * inv0),
                            __float2half_rn(c1[2][1] * inv0)),
                    pack_h2(__float2half_rn(c1[3][0] * inv0),
                            __float2half_rn(c1[3][1] * inv0)),
                    pack_h2(__float2half_rn(c1[2][2] * inv1),
                            __float2half_rn(c1[2][3] * inv1)),
                    pack_h2(__float2half_rn(c1[3][2] * inv1),
                            __float2half_rn(c1[3][3] * inv1)));
        }
        BARH(barid);

#pragma unroll
        for (int ns = 0; ns < 4; ++ns) {
            int n0 = ns * 16;
            uint32_t aaddr = p_base
                + (uint32_t)(n0 + ((l >> 4) & 1) * 8 + (l & 7)) * (PST * 2)
                + (m0c + ((l >> 3) & 1) * 8) * 2;
            uint32_t ah[4];
            ldsm_x4t(aaddr, ah);
#pragma unroll
            for (int q = 0; q < 4; ++q) {
                int k0 = kw * 64 + q * 16;
                uint32_t baddr = xh_base
                    + (uint32_t)(n0 + (l & 15)) * (XST * 2)
                    + (k0 + 8 * (l >> 4)) * 2;
                uint32_t bh[4];
                ldsm_x4t(baddr, bh);
                mma_f16(c2[2 * q],     ah, bh[0], bh[1]);
                mma_f16(c2[2 * q + 1], ah, bh[2], bh[3]);
            }
        }
    }

    {
        float* yo = &g_ypart[b][tile * 2 + h][0];
        int cr = m0c + (l >> 2);
#pragma unroll
        for (int q = 0; q < 4; ++q) {
            int k = kw * 64 + q * 16 + (l & 3) * 2;
            yo[cr * KDIM + k]            = c2[2 * q][0];
            yo[cr * KDIM + k + 1]        = c2[2 * q][1];
            yo[(cr + 8) * KDIM + k]      = c2[2 * q][2];
            yo[(cr + 8) * KDIM + k + 1]  = c2[2 * q][3];
            yo[cr * KDIM + k + 8]        = c2[2 * q + 1][0];
            yo[cr * KDIM + k + 9]        = c2[2 * q + 1][1];
            yo[(cr + 8) * KDIM + k + 8]  = c2[2 * q + 1][2];
            yo[(cr + 8) * KDIM + k + 9]  = c2[2 * q + 1][3];
        }
    }
}

// ============================================================
// Kernel 3: capsule-parallel finalize. grid (4, BATCH) = 512 CTAs, 512 thr.
// Each CTA: 8 capsules — reduce y partials, u = y@w, squash,
// then write output (last round) or W2 slice + fp16 split.
// ============================================================
__global__ void __launch_bounds__(512) k_fin(const float* __restrict__ w,
                                             float* __restrict__ out) {
    int b = blockIdx.y, g = blockIdx.x, t = threadIdx.x;
    int c0 = g * 8;                       // capsules c0..c0+7
    __shared__ float ys[8 * KDIM];        // 1024
    __shared__ float us[128];
    __shared__ float os[128];

    // reduce 16 partials for this capsule slice
#pragma unroll
    for (int i = 0; i < 2; ++i) {
        int li = t + i * 512;             // 0..1023
        int gi = c0 * KDIM + li;
        float s = 0.f;
#pragma unroll
        for (int p = 0; p < NPART; ++p) s += g_ypart[b][p][gi];
        ys[li] = s;
    }
    __syncthreads();

    // u[o] = sum_k ys[c_loc*128+k] * w[k][c0*16+o]; 4 threads per output
    {
        int o = t >> 2, part = t & 3;     // o in 0..127
        int cl = o >> 4;
        const float* yr = &ys[cl * KDIM];
        const float* wc = w + c0 * DCAP + o;
        float acc = 0.f;
        int kbeg = part * 32;
#pragma unroll 8
        for (int k = kbeg; k < kbeg + 32; ++k)
            acc += yr[k] * wc[k * MCOLS];
        acc += __shfl_xor_sync(0xffffffffu, acc, 1);
        acc += __shfl_xor_sync(0xffffffffu, acc, 2);
        if (part == 0) us[o] = acc;
    }
    __syncthreads();

    // squash per capsule (16-lane groups), write os / output
    if (t < 128) {
        float a = us[t];
        float sq = a * a;
#pragma unroll
        for (int off = 8; off >= 1; off >>= 1)
            sq += __shfl_xor_sync(0xffffffffu, sq, off, 16);
        float s2 = sq + 1e-7f;
        float scale = sqrtf(s2) / (0.5f + s2);
        float val = scale * a;
        os[t] = val;
        if (out) out[b * MCOLS + c0 * DCAP + t] = val;
    }
    __syncthreads();

    if (!out) {
        // W2 slice: rows c0..c0+7, fp16 hi/lo
#pragma unroll
        for (int i = 0; i < 2; ++i) {
            int idx = t + i * 512;        // 0..1023
            int cl = idx >> 7, k = idx & 127;
            int c = c0 + cl;
            const float4* wr = (const float4*)(w + k * MCOLS + c * DCAP);
            const float4* ov = (const float4*)(os + cl * DCAP);
            float acc = 0.f;
#pragma unroll
            for (int q = 0; q < 4; ++q) {
                float4 a = wr[q], o4 = ov[q];
                acc += a.x * o4.x + a.y * o4.y + a.z * o4.z + a.w * o4.w;
            }
            __half hh = __float2half_rn(acc);
            __half ll = __float2half_rn(acc - __half2float(hh));
            g_W2h[b][c * XST + k] = *(unsigned short*)&hh;
            g_W2l[b][c * XST + k] = *(unsigned short*)&ll;
        }
    }
}

extern "C" void kernel_launch(void* const* d_in, const int* in_sizes, int n_in,
                              void* d_out, int out_size) {
    const float* x = (const float*)d_in[0];
    const float* w = (const float*)d_in[1];
    if (n_in >= 2 && in_sizes[0] == MCOLS * KDIM) {
        x = (const float*)d_in[1];
        w = (const float*)d_in[0];
    }
    (void)out_size;

    cudaFuncSetAttribute(k_iter_mma, cudaFuncAttributeMaxDynamicSharedMemorySize,
                         SM_TOTAL);

    k_conv<<<dim3(2, BATCH), 512>>>(x);
    k_ow<<<BATCH, 512>>>(w);

    for (int r = 0; r < 2; ++r) {
        k_iter_mma<<<dim3(NTILES, BATCH), 256, SM_TOTAL>>>();
        k_fin<<<dim3(4, BATCH), 512>>>(w, (r == 1) ? (float*)d_out : nullptr);
    }
}